// round 6
// baseline (speedup 1.0000x reference)
#include <cuda_runtime.h>
#include <cuda_bf16.h>
#include <cstdint>

constexpr int B    = 32;
constexpr int H    = 1024;
constexpr int MEL  = 128;
constexpr int TENC = 512;
constexpr int TMEL = 400;
constexpr int H3   = 3 * H;

constexpr size_t OFF_GATE = (size_t)B * TMEL * MEL;
constexpr size_t OFF_MASK = OFF_GATE + (size_t)B * TMEL;

// ---------------- packed weights: P[cg][k][cl] = W[cg*32+cl][k] --------------
__device__ float Pih0[(size_t)H3 * MEL];      // 96 cg x 128 k x 32
__device__ float Phh0[(size_t)H3 * H];        // 96 cg x 1024 k x 32
__device__ float Pih1[(size_t)H3 * H];
__device__ float Phh1[(size_t)H3 * H];
__device__ float Pc  [(size_t)H * 2 * H];     // 32 cg x 2048 k x 32
__device__ float Pp6 [(size_t)160 * H];       // 5 cg x 1024 k x 32 (mel+gate)
__device__ float Pat [(size_t)H * H];         // W_attn^T packed: 32 cg x 1024 j x 32

// ---------------- states / partials ------------------------------------------
__device__ float g_h0[2][B * H];
__device__ float g_h1[2][B * H];
__device__ float g_decin[B * MEL];
__device__ float g_v[B * H];
__device__ float g_scores[B * TENC];
__device__ float g_ctx[B * H];
__device__ float g_co[B * H];

__device__ float pG[32][B][H3];               // GRU partials 12.6 MB
__device__ float vp[32][B * H];               // Pv partials   4.2 MB
__device__ float cp[64][B * H];               // P5 partials   8.4 MB
__device__ float p6p[32][B][160];             // P6 partials

// barriers
__device__ unsigned g_bar_arrive = 0;
__device__ volatile unsigned g_bar_gen = 0;
__device__ volatile unsigned g_slots[152 * 8];

// ---------------- helpers ----------------------------------------------------
__device__ __forceinline__ float wsum(float v) {
    v += __shfl_xor_sync(0xffffffffu, v, 16);
    v += __shfl_xor_sync(0xffffffffu, v, 8);
    v += __shfl_xor_sync(0xffffffffu, v, 4);
    v += __shfl_xor_sync(0xffffffffu, v, 2);
    v += __shfl_xor_sync(0xffffffffu, v, 1);
    return v;
}
__device__ __forceinline__ float wmax(float v) {
    v = fmaxf(v, __shfl_xor_sync(0xffffffffu, v, 16));
    v = fmaxf(v, __shfl_xor_sync(0xffffffffu, v, 8));
    v = fmaxf(v, __shfl_xor_sync(0xffffffffu, v, 4));
    v = fmaxf(v, __shfl_xor_sync(0xffffffffu, v, 2));
    v = fmaxf(v, __shfl_xor_sync(0xffffffffu, v, 1));
    return v;
}
__device__ __forceinline__ float sigmoidf_(float x) { return 1.f / (1.f + expf(-x)); }

// legacy atomic barrier (re-launch safe); used once after init
__device__ __forceinline__ void abar(int nblk) {
    __syncthreads();
    if (threadIdx.x == 0) {
        __threadfence();
        unsigned gen = g_bar_gen;
        if (atomicAdd(&g_bar_arrive, 1u) == (unsigned)nblk - 1u) {
            g_bar_arrive = 0;
            __threadfence();
            g_bar_gen = gen + 1u;
        } else {
            while (g_bar_gen == gen) {}
        }
        __threadfence();
    }
    __syncthreads();
}

// distributed-flag barrier: no atomic serialization
__device__ __forceinline__ void sbar(int nblk, int bx, unsigned gen) {
    __syncthreads();
    if (threadIdx.x < 32) {
        if (threadIdx.x == 0) {
            __threadfence();
            g_slots[bx * 8] = gen;
        }
        unsigned ok;
        do {
            ok = 1u;
            for (int i = threadIdx.x; i < nblk; i += 32)
                ok &= (g_slots[i * 8] >= gen) ? 1u : 0u;
        } while (__ballot_sync(0xffffffffu, ok == 0u));
        __threadfence();
    }
    __syncthreads();
}

// GEMM micro-kernel: lane owns one output column (within packed cg), all 32
// batches accumulate in registers. Weight loads stream contiguous 128B lines.
template<int XS>
__device__ __forceinline__ void gemm32(const float* __restrict__ Wt,
                                       const float* __restrict__ X,
                                       int klen, float* __restrict__ acc) {
#pragma unroll 1
    for (int k = 0; k < klen; k += 4) {
        float w0 = Wt[0], w1 = Wt[32], w2 = Wt[64], w3 = Wt[96];
        Wt += 128;
        const float* Xk = X + k;
#pragma unroll
        for (int bb = 0; bb < 32; ++bb) {
            float4 xv = *reinterpret_cast<const float4*>(Xk + (size_t)bb * XS);
            acc[bb] = fmaf(w0, xv.x, fmaf(w1, xv.y, fmaf(w2, xv.z, fmaf(w3, xv.w, acc[bb]))));
        }
    }
}

// pack: dst[tr][tc*32+y][x] = W[(tr*32+x)][tc*32+y]  via smem tile
__device__ void pack_mat(const float* __restrict__ src, float* __restrict__ dst,
                         int O, int K, int bx, int nblk, int tid,
                         float (*tile)[33]) {
    int x = tid & 31, y = tid >> 5;            // y in 0..15
    int ntr = O >> 5, ntc = K >> 5;
    for (int t = bx; t < ntr * ntc; t += nblk) {
        int tr = t / ntc, tc = t % ntc;
        __syncthreads();
        tile[y][x]      = src[(size_t)(tr * 32 + y) * K + tc * 32 + x];
        tile[y + 16][x] = src[(size_t)(tr * 32 + y + 16) * K + tc * 32 + x];
        __syncthreads();
        dst[(size_t)tr * K * 32 + (size_t)(tc * 32 + y) * 32 + x]      = tile[x][y];
        dst[(size_t)tr * K * 32 + (size_t)(tc * 32 + y + 16) * 32 + x] = tile[x][y + 16];
    }
}

// ---------------- main persistent kernel -------------------------------------
__global__ void __launch_bounds__(512, 1)
decoder_kernel(const float* __restrict__ enc_hidden,
               const float* __restrict__ enc_out,
               const int*   __restrict__ lens,
               const float* __restrict__ W_attn, const float* __restrict__ b_attn,
               const float* __restrict__ Wih0, const float* __restrict__ Whh0,
               const float* __restrict__ bih0, const float* __restrict__ bhh0,
               const float* __restrict__ Wih1, const float* __restrict__ Whh1,
               const float* __restrict__ bih1, const float* __restrict__ bhh1,
               const float* __restrict__ Wc,   const float* __restrict__ bc,
               const float* __restrict__ Wp,   const float* __restrict__ bp,
               const float* __restrict__ Wg,   const float* __restrict__ bg,
               float* __restrict__ out, int nblk) {
    __shared__ float tile[32][33];
    const int tid  = threadIdx.x;
    const int lane = tid & 31;
    const int wid  = tid >> 5;
    const int bx   = blockIdx.x;
    const int jw   = wid * nblk + bx;
    const int GW   = nblk * 16;
    const int gtid = bx * blockDim.x + tid;
    const int gsz  = nblk * blockDim.x;

    // ================= init: pack weights, states, mask =================
    pack_mat(Wih0, Pih0, H3, MEL,   bx, nblk, tid, tile);
    pack_mat(Whh0, Phh0, H3, H,     bx, nblk, tid, tile);
    pack_mat(Wih1, Pih1, H3, H,     bx, nblk, tid, tile);
    pack_mat(Whh1, Phh1, H3, H,     bx, nblk, tid, tile);
    pack_mat(Wc,   Pc,   H,  2 * H, bx, nblk, tid, tile);
    pack_mat(Wp,   Pp6,  MEL, H,    bx, nblk, tid, tile);   // cg 0..3

    // Pat[cg][j][cl] = W_attn[j][cg*32+cl]  (coalesced both sides)
    for (int d = gtid; d < H * H; d += gsz) {
        int cl = d & 31, j = (d >> 5) & (H - 1), cg = d >> 15;
        Pat[d] = W_attn[(size_t)j * H + cg * 32 + cl];
    }
    // Pp6 cg=4: gate row (cl==0 -> Wg, else 0)
    for (int d = gtid; d < H * 32; d += gsz) {
        int cl = d & 31, k = d >> 5;
        Pp6[(size_t)4 * H * 32 + d] = (cl == 0) ? Wg[k] : 0.f;
    }
    for (int i = gtid; i < B * H; i += gsz) {
        g_h0[0][i] = enc_hidden[i];
        g_h1[0][i] = enc_hidden[B * H + i];
    }
    for (int i = gtid; i < B * MEL; i += gsz) g_decin[i] = 0.f;
    for (int i = gtid; i < B * TMEL; i += gsz) {
        int b = i / TMEL, t = i - b * TMEL;
        out[OFF_MASK + i] = (t > lens[b]) ? 1.f : 0.f;
    }
    if (tid == 0) g_slots[bx * 8] = 0u;       // reset my slot (re-launch safety)
    abar(nblk);                               // atomic barrier: init complete

    unsigned gen = 0;

    // ================= 400 autoregressive steps =================
    for (int step = 0; step < TMEL; ++step) {
        const int cur = step & 1, nxt = cur ^ 1;

        // ---- A: GRU0 GEMMs (192 x-side + 1536 h-side jobs) ----
        for (int job = jw; job < 1728; job += GW) {
            float acc[32];
#pragma unroll
            for (int i = 0; i < 32; ++i) acc[i] = 0.f;
            int jg, slot;
            if (job < 192) {
                jg = job >> 1; int kc = job & 1; slot = kc;
                gemm32<MEL>(Pih0 + (size_t)jg * (MEL * 32) + kc * 64 * 32 + lane,
                            g_decin + kc * 64, 64, acc);
            } else {
                int q = job - 192;
                jg = q >> 4; int kc = q & 15; slot = 2 + kc;
                gemm32<H>(Phh0 + (size_t)jg * (H * 32) + kc * 64 * 32 + lane,
                          g_h0[cur] + kc * 64, 64, acc);
            }
            const int j = jg * 32 + lane;
#pragma unroll 4
            for (int bb = 0; bb < 32; ++bb) pG[slot][bb][j] = acc[bb];
        }
        sbar(nblk, bx, ++gen);

        // ---- B: combine GRU0 ----
        for (int idx = gtid; idx < B * H; idx += gsz) {
            int b = idx >> 10, c = idx & (H - 1);
            float sx[3], sh[3];
#pragma unroll
            for (int g = 0; g < 3; ++g) {
                int j = g * H + c;
                sx[g] = pG[0][b][j] + pG[1][b][j];
                float s = 0.f;
#pragma unroll
                for (int p = 2; p < 18; ++p) s += pG[p][b][j];
                sh[g] = s;
            }
            float r = sigmoidf_(sx[0] + sh[0] + bih0[c] + bhh0[c]);
            float z = sigmoidf_(sx[1] + sh[1] + bih0[H + c] + bhh0[H + c]);
            float n = tanhf(sx[2] + bih0[2 * H + c] + r * (sh[2] + bhh0[2 * H + c]));
            g_h0[nxt][idx] = (1.f - z) * n + z * g_h0[cur][idx];
        }
        sbar(nblk, bx, ++gen);

        // ---- C: GRU1 GEMMs (1536 + 1536 jobs) ----
        for (int job = jw; job < 3072; job += GW) {
            float acc[32];
#pragma unroll
            for (int i = 0; i < 32; ++i) acc[i] = 0.f;
            int jg, slot;
            if (job < 1536) {
                jg = job >> 4; int kc = job & 15; slot = kc;
                gemm32<H>(Pih1 + (size_t)jg * (H * 32) + kc * 64 * 32 + lane,
                          g_h0[nxt] + kc * 64, 64, acc);
            } else {
                int q = job - 1536;
                jg = q >> 4; int kc = q & 15; slot = 16 + kc;
                gemm32<H>(Phh1 + (size_t)jg * (H * 32) + kc * 64 * 32 + lane,
                          g_h1[cur] + kc * 64, 64, acc);
            }
            const int j = jg * 32 + lane;
#pragma unroll 4
            for (int bb = 0; bb < 32; ++bb) pG[slot][bb][j] = acc[bb];
        }
        sbar(nblk, bx, ++gen);

        // ---- D: combine GRU1 ----
        for (int idx = gtid; idx < B * H; idx += gsz) {
            int b = idx >> 10, c = idx & (H - 1);
            float sx[3], sh[3];
#pragma unroll
            for (int g = 0; g < 3; ++g) {
                int j = g * H + c;
                float s1 = 0.f, s2 = 0.f;
#pragma unroll
                for (int p = 0; p < 16; ++p) s1 += pG[p][b][j];
#pragma unroll
                for (int p = 16; p < 32; ++p) s2 += pG[p][b][j];
                sx[g] = s1; sh[g] = s2;
            }
            float r = sigmoidf_(sx[0] + sh[0] + bih1[c] + bhh1[c]);
            float z = sigmoidf_(sx[1] + sh[1] + bih1[H + c] + bhh1[H + c]);
            float n = tanhf(sx[2] + bih1[2 * H + c] + r * (sh[2] + bhh1[2 * H + c]));
            g_h1[nxt][idx] = (1.f - z) * n + z * g_h1[cur][idx];
        }
        sbar(nblk, bx, ++gen);

        const float* h1n = g_h1[nxt];

        // ---- E: Pv  v = W_attn^T h1  (1024 jobs, klen 32) ----
        for (int job = jw; job < 1024; job += GW) {
            int cg = job >> 5, kc = job & 31;
            float acc[32];
#pragma unroll
            for (int i = 0; i < 32; ++i) acc[i] = 0.f;
            gemm32<H>(Pat + (size_t)cg * (H * 32) + kc * 32 * 32 + lane,
                      h1n + kc * 32, 32, acc);
            const int c = cg * 32 + lane;
#pragma unroll 4
            for (int bb = 0; bb < 32; ++bb) vp[kc][bb * H + c] = acc[bb];
        }
        sbar(nblk, bx, ++gen);

        // ---- Ec: v = sum partials ----
        for (int idx = gtid; idx < B * H; idx += gsz) {
            float s = 0.f;
#pragma unroll
            for (int p = 0; p < 32; ++p) s += vp[p][idx];
            g_v[idx] = s;
        }
        sbar(nblk, bx, ++gen);

        // ---- P3: scores[b,t] = v[b,:] . enc_out[b,t,:]  (2048 jobs) ----
        for (int job = jw; job < 2048; job += GW) {
            const int b  = job >> 6;
            const int t0 = (job & 63) * 8;
            float acc[8];
#pragma unroll
            for (int i = 0; i < 8; ++i) acc[i] = 0.f;
            const float4* vb = reinterpret_cast<const float4*>(g_v + (size_t)b * H);
            const float4* Eb = reinterpret_cast<const float4*>(
                enc_out + ((size_t)b * TENC + t0) * H);
            for (int k = lane; k < 256; k += 32) {
                float4 vv = vb[k];
#pragma unroll
                for (int t = 0; t < 8; ++t) {
                    float4 ev = Eb[(size_t)t * 256 + k];
                    acc[t] = fmaf(vv.x, ev.x, fmaf(vv.y, ev.y,
                             fmaf(vv.z, ev.z, fmaf(vv.w, ev.w, acc[t]))));
                }
            }
#pragma unroll
            for (int t = 0; t < 8; ++t) {
                float s = wsum(acc[t]);
                if (lane == t) g_scores[b * TENC + t0 + t] = s;
            }
        }
        sbar(nblk, bx, ++gen);

        // ---- P4: softmax (per-warp) + context (1024 jobs) ----
        for (int job = jw; job < 1024; job += GW) {
            const int b  = job >> 5;
            const int hg = (job & 31) * 32;
            const float* srow = g_scores + b * TENC;
            float sc[16];
            float mx = -1e30f;
#pragma unroll
            for (int i = 0; i < 16; ++i) {
                sc[i] = srow[i * 32 + lane];
                mx = fmaxf(mx, sc[i]);
            }
            mx = wmax(mx);
            float sm = 0.f;
#pragma unroll
            for (int i = 0; i < 16; ++i) { sc[i] = expf(sc[i] - mx); sm += sc[i]; }
            sm = wsum(sm);
            const float inv = 1.f / sm;

            float acc = 0.f;
            const float* ep = enc_out + (size_t)b * TENC * H + hg + lane;
#pragma unroll
            for (int i = 0; i < 16; ++i) {
                float pv = sc[i] * inv;
#pragma unroll 8
                for (int tt = 0; tt < 32; ++tt) {
                    float p  = __shfl_sync(0xffffffffu, pv, tt);
                    float ev = ep[(size_t)(i * 32 + tt) * H];
                    acc = fmaf(p, ev, acc);
                }
            }
            g_ctx[(size_t)b * H + hg + lane] = acc;
        }
        sbar(nblk, bx, ++gen);

        // ---- P5: co GEMM over [h1; ctx] (2048 jobs, klen 32) ----
        for (int job = jw; job < 2048; job += GW) {
            int cg = job >> 6, kc = job & 63;
            float acc[32];
#pragma unroll
            for (int i = 0; i < 32; ++i) acc[i] = 0.f;
            const float* X = (kc < 32) ? (h1n + kc * 32) : (g_ctx + (kc - 32) * 32);
            gemm32<H>(Pc + (size_t)cg * (2 * H * 32) + kc * 32 * 32 + lane, X, 32, acc);
            const int c = cg * 32 + lane;
#pragma unroll 4
            for (int bb = 0; bb < 32; ++bb) cp[kc][bb * H + c] = acc[bb];
        }
        sbar(nblk, bx, ++gen);

        // ---- P5c: co = tanh(sum + bc) ----
        for (int idx = gtid; idx < B * H; idx += gsz) {
            int c = idx & (H - 1);
            float s = 0.f;
#pragma unroll
            for (int p = 0; p < 64; ++p) s += cp[p][idx];
            g_co[idx] = tanhf(s + bc[c]);
        }
        sbar(nblk, bx, ++gen);

        // ---- P6: mel/gate GEMM (160 jobs, klen 32) ----
        for (int job = jw; job < 160; job += GW) {
            int cg = job % 5, kc = job / 5;
            float acc[32];
#pragma unroll
            for (int i = 0; i < 32; ++i) acc[i] = 0.f;
            gemm32<H>(Pp6 + (size_t)cg * (H * 32) + kc * 32 * 32 + lane,
                      g_co + kc * 32, 32, acc);
            const int c = cg * 32 + lane;
#pragma unroll 4
            for (int bb = 0; bb < 32; ++bb) p6p[kc][bb][c] = acc[bb];
        }
        sbar(nblk, bx, ++gen);

        // ---- P6c: bias + mask + outputs + next decoder input ----
        for (int idx = gtid; idx < B * 160; idx += gsz) {
            int b = idx / 160, m = idx - b * 160;
            if (m > MEL) continue;
            float s = 0.f;
#pragma unroll
            for (int p = 0; p < 32; ++p) s += p6p[p][b][m];
            const bool msk = step > lens[b];
            if (m < MEL) {
                float val = s + bp[m];
                g_decin[b * MEL + m] = val;
                out[((size_t)b * TMEL + step) * MEL + m] = msk ? 0.f : val;
            } else {
                float gv = s + bg[0];
                out[OFF_GATE + (size_t)b * TMEL + step] = msk ? 1000.f : gv;
            }
        }
        sbar(nblk, bx, ++gen);
    }
}

// ---------------- host launch -------------------------------------------------
extern "C" void kernel_launch(void* const* d_in, const int* in_sizes, int n_in,
                              void* d_out, int out_size) {
    (void)in_sizes; (void)n_in; (void)out_size;
    int dev = 0;
    cudaGetDevice(&dev);
    int sms = 0;
    cudaDeviceGetAttribute(&sms, cudaDevAttrMultiProcessorCount, dev);
    if (sms <= 0) sms = 148;
    if (sms > 152) sms = 152;

    decoder_kernel<<<sms, 512>>>(
        (const float*)d_in[0],   // encoder_hidden [4,B,H]
        (const float*)d_in[1],   // encoder_outputs [B,TENC,H]
        (const int*)d_in[3],     // mel_spec_lens [B]   (d_in[2] = y, unused)
        (const float*)d_in[4],  (const float*)d_in[5],    // W_attn, b_attn
        (const float*)d_in[6],  (const float*)d_in[7],    // W_ih0, W_hh0
        (const float*)d_in[8],  (const float*)d_in[9],    // b_ih0, b_hh0
        (const float*)d_in[10], (const float*)d_in[11],   // W_ih1, W_hh1
        (const float*)d_in[12], (const float*)d_in[13],   // b_ih1, b_hh1
        (const float*)d_in[14], (const float*)d_in[15],   // Wc, bc
        (const float*)d_in[16], (const float*)d_in[17],   // Wp, bp
        (const float*)d_in[18], (const float*)d_in[19],   // Wg, bg
        (float*)d_out, sms);
}